// round 10
// baseline (speedup 1.0000x reference)
#include <cuda_runtime.h>
#include <cstdint>
#include <math.h>

#define BB 4
#define SS 2048
#define DD 1024
#define FF 4096

// ---------------- scratch (__device__ globals; no allocs allowed) --------
__device__ float g_ln1[(size_t)BB * SS * DD];
__device__ float g_Q  [(size_t)BB * SS * DD];
__device__ float g_K  [(size_t)BB * SS * DD];
__device__ float g_Vt [(size_t)BB * DD * SS];   // V transposed: [b][d][s]
__device__ float g_S  [(size_t)BB * SS * SS];
__device__ float g_x1 [(size_t)BB * SS * DD];
__device__ float g_ln2[(size_t)BB * SS * DD];
__device__ float g_H  [(size_t)BB * SS * FF];
__device__ float g_Qwt[(size_t)DD * DD];
__device__ float g_Kwt[(size_t)DD * DD];
__device__ float g_Vwt[(size_t)DD * DD];
__device__ float g_w1t[(size_t)DD * FF];
__device__ float g_w2t[(size_t)DD * FF];

// ---------------- helpers -------------------------------------------------
__device__ __forceinline__ uint32_t smem_u32(const void* p) {
    uint32_t a;
    asm("{ .reg .u64 t; cvta.to.shared.u64 t, %1; cvt.u32.u64 %0, t; }"
        : "=r"(a) : "l"(p));
    return a;
}
__device__ __forceinline__ float rna_tf32(float x) {
    uint32_t u;
    asm("cvt.rna.tf32.f32 %0, %1;" : "=r"(u) : "f"(x));
    return __uint_as_float(u);
}
__device__ __forceinline__ void cpa16(uint32_t dst, const void* src) {
    asm volatile("cp.async.cg.shared.global [%0], [%1], 16;\n"
                 :: "r"(dst), "l"(src));
}
__device__ __forceinline__ void cp_commit() {
    asm volatile("cp.async.commit_group;\n" ::: "memory");
}
__device__ __forceinline__ void cp_wait1() {
    asm volatile("cp.async.wait_group 1;\n" ::: "memory");
}
__device__ __forceinline__ void cp_wait0() {
    asm volatile("cp.async.wait_group 0;\n" ::: "memory");
}
__device__ __forceinline__ void mma_tf32_16n8k8(
    float& d0, float& d1, float& d2, float& d3,
    uint32_t a0, uint32_t a1, uint32_t a2, uint32_t a3,
    uint32_t b0, uint32_t b1)
{
    asm volatile(
        "mma.sync.aligned.m16n8k8.row.col.f32.tf32.tf32.f32 "
        "{%0,%1,%2,%3}, {%4,%5,%6,%7}, {%8,%9}, {%0,%1,%2,%3};"
        : "+f"(d0), "+f"(d1), "+f"(d2), "+f"(d3)
        : "r"(a0), "r"(a1), "r"(a2), "r"(a3), "r"(b0), "r"(b1));
}

// ---------------- LayerNorm (rounded-to-tf32 output) ---------------------
__global__ __launch_bounds__(256)
void layernorm_kernel(const float* __restrict__ x,
                      const float* __restrict__ gamma,
                      const float* __restrict__ beta,
                      float* __restrict__ out)
{
    const int row = blockIdx.x;
    const int tid = threadIdx.x;
    float4 v = ((const float4*)(x + (size_t)row * DD))[tid];

    float s  = v.x + v.y + v.z + v.w;
    float sq = v.x * v.x + v.y * v.y + v.z * v.z + v.w * v.w;
    __shared__ float ws[8], wq[8];
    #pragma unroll
    for (int o = 16; o; o >>= 1) {
        s  += __shfl_xor_sync(0xffffffffu, s,  o);
        sq += __shfl_xor_sync(0xffffffffu, sq, o);
    }
    const int w = tid >> 5, l = tid & 31;
    if (l == 0) { ws[w] = s; wq[w] = sq; }
    __syncthreads();
    if (w == 0) {
        s  = (l < 8) ? ws[l] : 0.f;
        sq = (l < 8) ? wq[l] : 0.f;
        #pragma unroll
        for (int o = 4; o; o >>= 1) {
            s  += __shfl_xor_sync(0xffffffffu, s,  o);
            sq += __shfl_xor_sync(0xffffffffu, sq, o);
        }
        if (l == 0) { ws[0] = s; wq[0] = sq; }
    }
    __syncthreads();
    const float mean = ws[0] * (1.f / (float)DD);
    const float var  = wq[0] * (1.f / (float)DD) - mean * mean;
    const float rstd = rsqrtf(var + 1e-5f);
    float4 g = ((const float4*)gamma)[tid];
    float4 b = ((const float4*)beta )[tid];
    float4 o4;
    o4.x = rna_tf32(g.x * ((v.x - mean) * rstd) + b.x);
    o4.y = rna_tf32(g.y * ((v.y - mean) * rstd) + b.y);
    o4.z = rna_tf32(g.z * ((v.z - mean) * rstd) + b.z);
    o4.w = rna_tf32(g.w * ((v.w - mean) * rstd) + b.w);
    ((float4*)(out + (size_t)row * DD))[tid] = o4;
}

// ---------------- causal softmax (rounded output, 256-pad zeroed) --------
__global__ __launch_bounds__(256)
void softmax_kernel(float* __restrict__ scores)
{
    const int row = blockIdx.x;
    const int b = row >> 11;
    const int i = row & (SS - 1);
    float* p = scores + (size_t)b * SS * SS + (size_t)i * SS;
    const int len = i + 1;
    const int tid = threadIdx.x;
    __shared__ float sh[8];

    float m = -1e30f;
    for (int j = tid; j < len; j += 256) m = fmaxf(m, p[j]);
    #pragma unroll
    for (int o = 16; o; o >>= 1) m = fmaxf(m, __shfl_xor_sync(0xffffffffu, m, o));
    const int w = tid >> 5, l = tid & 31;
    if (l == 0) sh[w] = m;
    __syncthreads();
    if (w == 0) {
        m = (l < 8) ? sh[l] : -1e30f;
        #pragma unroll
        for (int o = 4; o; o >>= 1) m = fmaxf(m, __shfl_xor_sync(0xffffffffu, m, o));
        if (l == 0) sh[0] = m;
    }
    __syncthreads();
    m = sh[0];
    __syncthreads();

    float sum = 0.f;
    for (int j = tid; j < len; j += 256) {
        float e = __expf(p[j] - m);
        p[j] = e;
        sum += e;
    }
    #pragma unroll
    for (int o = 16; o; o >>= 1) sum += __shfl_xor_sync(0xffffffffu, sum, o);
    if (l == 0) sh[w] = sum;
    __syncthreads();
    if (w == 0) {
        sum = (l < 8) ? sh[l] : 0.f;
        #pragma unroll
        for (int o = 4; o; o >>= 1) sum += __shfl_xor_sync(0xffffffffu, sum, o);
        if (l == 0) sh[0] = sum;
    }
    __syncthreads();
    const float inv = 1.f / sh[0];
    // zero-pad to the 256 boundary: the K-limited P@V GEMM (BM=256) reads
    // k < m0+256 for every row of its tile.
    const int lenp = (len + 255) & ~255;
    for (int j = tid; j < lenp; j += 256)
        p[j] = (j < len) ? rna_tf32(p[j] * inv) : 0.f;
}

// ---------------- transpose (rounded): in[R,C] -> out[C,R] ----------------
__global__ __launch_bounds__(256)
void transpose_kernel(const float* __restrict__ in, float* __restrict__ out,
                      int R, int C)
{
    __shared__ float t[32][33];
    const int c0 = blockIdx.x * 32, r0 = blockIdx.y * 32;
    const int x = threadIdx.x, y = threadIdx.y;
    #pragma unroll
    for (int i = 0; i < 32; i += 8)
        t[y + i][x] = in[(size_t)(r0 + y + i) * C + c0 + x];
    __syncthreads();
    #pragma unroll
    for (int i = 0; i < 32; i += 8)
        out[(size_t)(c0 + y + i) * R + r0 + x] = rna_tf32(t[x][y + i]);
}

// ---------------- tf32 mma.sync GEMM: C[M,N] = A[M,K] * B[N,K]^T ----------
// CTA tile 256x128x32, 8 warps (4m x 2n), warp tile 64x64, 3-stage cp.async
// pipeline + register double-buffered fragments (LDS for ks+1 overlaps MMA
// for ks). SMEM row stride 36 floats -> conflict-free fragment loads.
// EPI: 0=none 1=alpha 2=bias+relu 3=bias+res 4=res.
#define BM 256
#define BN 128
#define BK 32
#define SST 36                          // smem row stride (floats)
static constexpr int TILE_A_BYTES = BM * SST * 4;          // 36864
static constexpr int TILE_B_BYTES = BN * SST * 4;          // 18432
static constexpr int STAGE_BYTES  = TILE_A_BYTES + TILE_B_BYTES;  // 55296
static constexpr int NSTAGE       = 3;
static constexpr int SMEM_TOT     = NSTAGE * STAGE_BYTES;  // 165888

template <int EPI, bool RND, bool CSKIP, bool KLIM>
__global__ __launch_bounds__(256)
void mma_gemm(const float* __restrict__ Ag, const float* __restrict__ Bg,
              float* __restrict__ Cg, const float* __restrict__ bias,
              const float* __restrict__ Rg,
              int K, int lda, int ldb, int ldc,
              long long sA, long long sB, long long sC, long long sR,
              float alpha)
{
    const int m0 = blockIdx.y * BM, n0 = blockIdx.x * BN, bz = blockIdx.z;
    if (CSKIP && n0 >= m0 + BM) return;
    Ag += (size_t)bz * sA;
    Bg += (size_t)bz * sB;
    Cg += (size_t)bz * sC;
    if (EPI == 3 || EPI == 4) Rg += (size_t)bz * sR;

    extern __shared__ char smem[];
    const uint32_t sb = smem_u32(smem);
    float* sf = (float*)smem;

    const int tid  = threadIdx.x;
    const int wid  = tid >> 5;
    const int lane = tid & 31;
    const int wm   = (wid >> 1) * 64;    // warp m offset (0,64,128,192)
    const int wn   = (wid & 1) * 64;     // warp n offset (0,64)
    const int lr   = lane >> 2;          // 0..7
    const int lc   = lane & 3;           // 0..3

    int kend = K;
    if (KLIM) { int lim = m0 + BM; kend = lim < K ? lim : K; }
    const int T = kend >> 5;

    float acc[4][8][4];
    #pragma unroll
    for (int mi = 0; mi < 4; mi++)
        #pragma unroll
        for (int ni = 0; ni < 8; ni++)
            #pragma unroll
            for (int q = 0; q < 4; q++) acc[mi][ni][q] = 0.f;

    // A: 256 rows x 8 float4-chunks = 2048 chunks; 8 per thread
    auto cpA = [&](int t, int slot) {
        const float* base = Ag + (size_t)m0 * lda + t * BK;
        const uint32_t db = sb + slot * STAGE_BYTES;
        #pragma unroll
        for (int it = 0; it < 8; it++) {
            const int idx = tid + it * 256;
            const int r = idx >> 3, c4 = idx & 7;
            cpa16(db + (uint32_t)(r * (SST * 4) + c4 * 16),
                  base + (size_t)r * lda + c4 * 4);
        }
    };
    // B: 128 rows x 8 chunks = 1024 chunks; 4 per thread
    auto cpB = [&](int t, int slot) {
        const float* base = Bg + (size_t)n0 * ldb + t * BK;
        const uint32_t db = sb + slot * STAGE_BYTES + TILE_A_BYTES;
        #pragma unroll
        for (int it = 0; it < 4; it++) {
            const int idx = tid + it * 256;
            const int r = idx >> 3, c4 = idx & 7;
            cpa16(db + (uint32_t)(r * (SST * 4) + c4 * 16),
                  base + (size_t)r * ldb + c4 * 4);
        }
    };

    // double-buffered register fragments
    uint32_t af[2][4][4], bf[2][8][2];

    auto ldfrag = [&](const float* sa, const float* sbb, int ks, int pb) {
        const int kb = ks * 8;
        #pragma unroll
        for (int mi = 0; mi < 4; mi++) {
            const int r = wm + mi * 16 + lr;
            af[pb][mi][0] = __float_as_uint(sa[(r    ) * SST + kb + lc    ]);
            af[pb][mi][1] = __float_as_uint(sa[(r + 8) * SST + kb + lc    ]);
            af[pb][mi][2] = __float_as_uint(sa[(r    ) * SST + kb + lc + 4]);
            af[pb][mi][3] = __float_as_uint(sa[(r + 8) * SST + kb + lc + 4]);
        }
        #pragma unroll
        for (int ni = 0; ni < 8; ni++) {
            const int n = wn + ni * 8 + lr;
            bf[pb][ni][0] = __float_as_uint(sbb[n * SST + kb + lc    ]);
            bf[pb][ni][1] = __float_as_uint(sbb[n * SST + kb + lc + 4]);
        }
    };

    // prologue: stages 0 and 1, separate commit groups
    cpA(0, 0); cpB(0, 0); cp_commit();
    if (T > 1) { cpA(1, 1); cpB(1, 1); cp_commit(); }

    int slot = 0;
    for (int i = 0; i < T; i++) {
        if (i < T - 1) cp_wait1(); else cp_wait0();
        __syncthreads();

        const float* sa  = sf + (size_t)slot * (STAGE_BYTES / 4);
        const float* sbb = sa + (TILE_A_BYTES / 4);

        // critical path first: fragments for ks=0
        ldfrag(sa, sbb, 0, 0);

        // then overlap: prefetch stage i+2 while MMAs run
        if (i + 2 < T) {
            const int ns = (slot + 2) % NSTAGE;
            cpA(i + 2, ns); cpB(i + 2, ns); cp_commit();
        }

        #pragma unroll
        for (int ks = 0; ks < 4; ks++) {
            const int pb = ks & 1;
            if (ks < 3) ldfrag(sa, sbb, ks + 1, pb ^ 1);
            #pragma unroll
            for (int mi = 0; mi < 4; mi++)
                #pragma unroll
                for (int ni = 0; ni < 8; ni++)
                    mma_tf32_16n8k8(acc[mi][ni][0], acc[mi][ni][1],
                                    acc[mi][ni][2], acc[mi][ni][3],
                                    af[pb][mi][0], af[pb][mi][1],
                                    af[pb][mi][2], af[pb][mi][3],
                                    bf[pb][ni][0], bf[pb][ni][1]);
        }
        slot = (slot + 1) % NSTAGE;
    }

    // ---- epilogue: d0,d1 -> (row, col..col+1); d2,d3 -> (row+8, ...) ----
    #pragma unroll
    for (int mi = 0; mi < 4; mi++) {
        const int r0 = m0 + wm + mi * 16 + lr;
        #pragma unroll
        for (int ni = 0; ni < 8; ni++) {
            const int col = n0 + wn + ni * 8 + 2 * lc;
            #pragma unroll
            for (int h = 0; h < 2; h++) {
                const int r = r0 + h * 8;
                float vx = acc[mi][ni][2 * h + 0];
                float vy = acc[mi][ni][2 * h + 1];
                const size_t off = (size_t)r * ldc + col;
                if (EPI == 1) {
                    vx *= alpha; vy *= alpha;
                } else if (EPI == 2) {
                    vx = fmaxf(vx + __ldg(bias + col + 0), 0.f);
                    vy = fmaxf(vy + __ldg(bias + col + 1), 0.f);
                } else if (EPI == 3) {
                    float2 rr = *(const float2*)(Rg + off);
                    vx += __ldg(bias + col + 0) + rr.x;
                    vy += __ldg(bias + col + 1) + rr.y;
                } else if (EPI == 4) {
                    float2 rr = *(const float2*)(Rg + off);
                    vx += rr.x; vy += rr.y;
                }
                if (RND) { vx = rna_tf32(vx); vy = rna_tf32(vy); }
                float2 o2; o2.x = vx; o2.y = vy;
                *(float2*)(Cg + off) = o2;
            }
        }
    }
}

// ---------------- launcher ------------------------------------------------
extern "C" void kernel_launch(void* const* d_in, const int* in_sizes, int n_in,
                              void* d_out, int out_size)
{
    (void)in_sizes; (void)n_in; (void)out_size;
    const float* x      = (const float*)d_in[0];
    const float* Qw     = (const float*)d_in[1];
    const float* Kw     = (const float*)d_in[2];
    const float* Vw     = (const float*)d_in[3];
    const float* w1     = (const float*)d_in[4];
    const float* b1     = (const float*)d_in[5];
    const float* w2     = (const float*)d_in[6];
    const float* b2     = (const float*)d_in[7];
    const float* gamma1 = (const float*)d_in[8];
    const float* beta1  = (const float*)d_in[9];
    const float* gamma2 = (const float*)d_in[10];
    const float* beta2  = (const float*)d_in[11];
    float* out = (float*)d_out;

    float *pln1, *pQ, *pK, *pVt, *pS, *px1, *pln2, *pH;
    float *pQwt, *pKwt, *pVwt, *pw1t, *pw2t;
    cudaGetSymbolAddress((void**)&pln1, g_ln1);
    cudaGetSymbolAddress((void**)&pQ,   g_Q);
    cudaGetSymbolAddress((void**)&pK,   g_K);
    cudaGetSymbolAddress((void**)&pVt,  g_Vt);
    cudaGetSymbolAddress((void**)&pS,   g_S);
    cudaGetSymbolAddress((void**)&px1,  g_x1);
    cudaGetSymbolAddress((void**)&pln2, g_ln2);
    cudaGetSymbolAddress((void**)&pH,   g_H);
    cudaGetSymbolAddress((void**)&pQwt, g_Qwt);
    cudaGetSymbolAddress((void**)&pKwt, g_Kwt);
    cudaGetSymbolAddress((void**)&pVwt, g_Vwt);
    cudaGetSymbolAddress((void**)&pw1t, g_w1t);
    cudaGetSymbolAddress((void**)&pw2t, g_w2t);

    cudaFuncSetAttribute(mma_gemm<0, true,  false, false>,
        cudaFuncAttributeMaxDynamicSharedMemorySize, SMEM_TOT);
    cudaFuncSetAttribute(mma_gemm<1, false, true,  false>,
        cudaFuncAttributeMaxDynamicSharedMemorySize, SMEM_TOT);
    cudaFuncSetAttribute(mma_gemm<4, false, false, true>,
        cudaFuncAttributeMaxDynamicSharedMemorySize, SMEM_TOT);
    cudaFuncSetAttribute(mma_gemm<2, true,  false, false>,
        cudaFuncAttributeMaxDynamicSharedMemorySize, SMEM_TOT);
    cudaFuncSetAttribute(mma_gemm<3, false, false, false>,
        cudaFuncAttributeMaxDynamicSharedMemorySize, SMEM_TOT);

    const int MR = BB * SS;                 // 8192
    const long long SD  = (long long)SS * DD;
    const long long SSq = (long long)SS * SS;
    const long long DS  = (long long)DD * SS;
    dim3 tb(32, 8);

    // 0) weight transposes (K-major B operands), rounded to tf32
    transpose_kernel<<<dim3(DD / 32, DD / 32), tb>>>(Qw, pQwt, DD, DD);
    transpose_kernel<<<dim3(DD / 32, DD / 32), tb>>>(Kw, pKwt, DD, DD);
    transpose_kernel<<<dim3(DD / 32, DD / 32), tb>>>(Vw, pVwt, DD, DD);
    transpose_kernel<<<dim3(FF / 32, DD / 32), tb>>>(w1, pw1t, DD, FF);
    transpose_kernel<<<dim3(DD / 32, FF / 32), tb>>>(w2, pw2t, FF, DD);

    // 1) LN1
    layernorm_kernel<<<MR, 256>>>(x, gamma1, beta1, pln1);

    // 2) Q = ln1 @ Qw ; K = ln1 @ Kw   (M=8192, N=1024, K=1024)
    dim3 gq(DD / BN, MR / BM, 1);
    mma_gemm<0, true, false, false><<<gq, 256, SMEM_TOT>>>(
        pln1, pQwt, pQ, nullptr, nullptr, DD, DD, DD, DD, 0, 0, 0, 0, 1.f);
    mma_gemm<0, true, false, false><<<gq, 256, SMEM_TOT>>>(
        pln1, pKwt, pK, nullptr, nullptr, DD, DD, DD, DD, 0, 0, 0, 0, 1.f);

    // 3) Vt[b,d,s] = sum_k Vwt[d,k] * ln1[b,s,k]   (M=1024, N=2048 per batch)
    dim3 gv(SS / BN, DD / BM, BB);
    mma_gemm<0, true, false, false><<<gv, 256, SMEM_TOT>>>(
        pVwt, pln1, pVt, nullptr, nullptr, DD, DD, DD, SS, 0, SD, DS, 0, 1.f);

    // 4) scores = Q @ K^T / 32, causal tiles only  (M=N=2048, K=1024)
    dim3 gs(SS / BN, SS / BM, BB);
    mma_gemm<1, false, true, false><<<gs, 256, SMEM_TOT>>>(
        pQ, pK, pS, nullptr, nullptr, DD, DD, DD, SS, SD, SD, SSq, 0, 0.03125f);

    // 5) causal softmax (rounded, zero-padded to 256 boundary)
    softmax_kernel<<<MR, 256>>>(pS);

    // 6) x1 = P @ V + x    (M=2048, N=1024, K<=row band, per batch)
    dim3 gp(DD / BN, SS / BM, BB);
    mma_gemm<4, false, false, true><<<gp, 256, SMEM_TOT>>>(
        pS, pVt, px1, nullptr, x, SS, SS, SS, DD, SSq, DS, SD, SD, 1.f);

    // 7) LN2
    layernorm_kernel<<<MR, 256>>>(px1, gamma2, beta2, pln2);

    // 8) H = relu(ln2 @ w1 + b1)   (M=8192, N=4096, K=1024)
    dim3 g1(FF / BN, MR / BM, 1);
    mma_gemm<2, true, false, false><<<g1, 256, SMEM_TOT>>>(
        pln2, pw1t, pH, b1, nullptr, DD, DD, DD, FF, 0, 0, 0, 0, 1.f);

    // 9) out = H @ w2 + b2 + x1    (M=8192, N=1024, K=4096)
    dim3 g2(DD / BN, MR / BM, 1);
    mma_gemm<3, false, false, false><<<g2, 256, SMEM_TOT>>>(
        pH, pw2t, out, b2, px1, FF, FF, FF, DD, 0, 0, 0, 0, 1.f);
}

// round 13
// speedup vs baseline: 1.6342x; 1.6342x over previous
#include <cuda_runtime.h>
#include <cuda_fp16.h>
#include <cstdint>
#include <math.h>

#define BB 4
#define SS 2048
#define DD 1024
#define FF 4096

// ---------------- scratch (__device__ globals; no allocs allowed) --------
// GEMM operands/outputs in fp16; residual path in fp32.
__device__ __half g_ln1[(size_t)BB * SS * DD];
__device__ __half g_Q  [(size_t)BB * SS * DD];
__device__ __half g_K  [(size_t)BB * SS * DD];
__device__ __half g_Vt [(size_t)BB * DD * SS];   // V transposed: [b][d][s]
__device__ __half g_S  [(size_t)BB * SS * SS];
__device__ float  g_x1 [(size_t)BB * SS * DD];
__device__ __half g_ln2[(size_t)BB * SS * DD];
__device__ __half g_H  [(size_t)BB * SS * FF];
__device__ __half g_Qwt[(size_t)DD * DD];
__device__ __half g_Kwt[(size_t)DD * DD];
__device__ __half g_Vwt[(size_t)DD * DD];
__device__ __half g_w1t[(size_t)DD * FF];
__device__ __half g_w2t[(size_t)DD * FF];

// ---------------- helpers -------------------------------------------------
__device__ __forceinline__ uint32_t smem_u32(const void* p) {
    uint32_t a;
    asm("{ .reg .u64 t; cvta.to.shared.u64 t, %1; cvt.u32.u64 %0, t; }"
        : "=r"(a) : "l"(p));
    return a;
}
__device__ __forceinline__ void cpa16(uint32_t dst, const void* src) {
    asm volatile("cp.async.cg.shared.global [%0], [%1], 16;\n"
                 :: "r"(dst), "l"(src));
}
__device__ __forceinline__ void cp_commit() {
    asm volatile("cp.async.commit_group;\n" ::: "memory");
}
__device__ __forceinline__ void cp_wait1() {
    asm volatile("cp.async.wait_group 1;\n" ::: "memory");
}
__device__ __forceinline__ void cp_wait0() {
    asm volatile("cp.async.wait_group 0;\n" ::: "memory");
}
__device__ __forceinline__ void mma_f16_16816(
    float& d0, float& d1, float& d2, float& d3,
    uint32_t a0, uint32_t a1, uint32_t a2, uint32_t a3,
    uint32_t b0, uint32_t b1)
{
    asm volatile(
        "mma.sync.aligned.m16n8k16.row.col.f32.f16.f16.f32 "
        "{%0,%1,%2,%3}, {%4,%5,%6,%7}, {%8,%9}, {%0,%1,%2,%3};"
        : "+f"(d0), "+f"(d1), "+f"(d2), "+f"(d3)
        : "r"(a0), "r"(a1), "r"(a2), "r"(a3), "r"(b0), "r"(b1));
}

// ---------------- LayerNorm (fp32 in -> fp16 out) -------------------------
__global__ __launch_bounds__(256)
void layernorm_kernel(const float* __restrict__ x,
                      const float* __restrict__ gamma,
                      const float* __restrict__ beta,
                      __half* __restrict__ out)
{
    const int row = blockIdx.x;
    const int tid = threadIdx.x;
    float4 v = ((const float4*)(x + (size_t)row * DD))[tid];

    float s  = v.x + v.y + v.z + v.w;
    float sq = v.x * v.x + v.y * v.y + v.z * v.z + v.w * v.w;
    __shared__ float ws[8], wq[8];
    #pragma unroll
    for (int o = 16; o; o >>= 1) {
        s  += __shfl_xor_sync(0xffffffffu, s,  o);
        sq += __shfl_xor_sync(0xffffffffu, sq, o);
    }
    const int w = tid >> 5, l = tid & 31;
    if (l == 0) { ws[w] = s; wq[w] = sq; }
    __syncthreads();
    if (w == 0) {
        s  = (l < 8) ? ws[l] : 0.f;
        sq = (l < 8) ? wq[l] : 0.f;
        #pragma unroll
        for (int o = 4; o; o >>= 1) {
            s  += __shfl_xor_sync(0xffffffffu, s,  o);
            sq += __shfl_xor_sync(0xffffffffu, sq, o);
        }
        if (l == 0) { ws[0] = s; wq[0] = sq; }
    }
    __syncthreads();
    const float mean = ws[0] * (1.f / (float)DD);
    const float var  = wq[0] * (1.f / (float)DD) - mean * mean;
    const float rstd = rsqrtf(var + 1e-5f);
    float4 g = ((const float4*)gamma)[tid];
    float4 b = ((const float4*)beta )[tid];
    __half2 h0 = __floats2half2_rn(g.x * ((v.x - mean) * rstd) + b.x,
                                   g.y * ((v.y - mean) * rstd) + b.y);
    __half2 h1 = __floats2half2_rn(g.z * ((v.z - mean) * rstd) + b.z,
                                   g.w * ((v.w - mean) * rstd) + b.w);
    __half2* o2 = (__half2*)(out + (size_t)row * DD) + tid * 2;
    o2[0] = h0; o2[1] = h1;
}

// ---------------- causal softmax on fp16 scores (256-pad zeroed) ---------
__global__ __launch_bounds__(256)
void softmax_kernel(__half* __restrict__ scores)
{
    const int row = blockIdx.x;
    const int b = row >> 11;
    const int i = row & (SS - 1);
    __half* p = scores + (size_t)b * SS * SS + (size_t)i * SS;
    const int len = i + 1;
    const int tid = threadIdx.x;
    __shared__ float sh[8];

    float m = -1e30f;
    for (int j = tid; j < len; j += 256) m = fmaxf(m, __half2float(p[j]));
    #pragma unroll
    for (int o = 16; o; o >>= 1) m = fmaxf(m, __shfl_xor_sync(0xffffffffu, m, o));
    const int w = tid >> 5, l = tid & 31;
    if (l == 0) sh[w] = m;
    __syncthreads();
    if (w == 0) {
        m = (l < 8) ? sh[l] : -1e30f;
        #pragma unroll
        for (int o = 4; o; o >>= 1) m = fmaxf(m, __shfl_xor_sync(0xffffffffu, m, o));
        if (l == 0) sh[0] = m;
    }
    __syncthreads();
    m = sh[0];
    __syncthreads();

    float sum = 0.f;
    for (int j = tid; j < len; j += 256)
        sum += __expf(__half2float(p[j]) - m);
    #pragma unroll
    for (int o = 16; o; o >>= 1) sum += __shfl_xor_sync(0xffffffffu, sum, o);
    if (l == 0) sh[w] = sum;
    __syncthreads();
    if (w == 0) {
        sum = (l < 8) ? sh[l] : 0.f;
        #pragma unroll
        for (int o = 4; o; o >>= 1) sum += __shfl_xor_sync(0xffffffffu, sum, o);
        if (l == 0) sh[0] = sum;
    }
    __syncthreads();
    const float inv = 1.f / sh[0];
    // zero-pad to the 256 boundary: the K-limited P@V GEMM (BM=256) reads
    // k < m0+256 for every row of its tile.
    const int lenp = (len + 255) & ~255;
    for (int j = tid; j < lenp; j += 256) {
        float e = (j < len) ? __expf(__half2float(p[j]) - m) * inv : 0.f;
        p[j] = __float2half_rn(e);
    }
}

// ---------------- transpose: fp32 in[R,C] -> fp16 out[C,R] ----------------
__global__ __launch_bounds__(256)
void transpose_kernel(const float* __restrict__ in, __half* __restrict__ out,
                      int R, int C)
{
    __shared__ float t[32][33];
    const int c0 = blockIdx.x * 32, r0 = blockIdx.y * 32;
    const int x = threadIdx.x, y = threadIdx.y;
    #pragma unroll
    for (int i = 0; i < 32; i += 8)
        t[y + i][x] = in[(size_t)(r0 + y + i) * C + c0 + x];
    __syncthreads();
    #pragma unroll
    for (int i = 0; i < 32; i += 8)
        out[(size_t)(c0 + y + i) * R + r0 + x] = __float2half_rn(t[x][y + i]);
}

// ---------------- fp16 mma.sync GEMM: C[M,N] = A[M,K] * B[N,K]^T ----------
// CTA tile 256x128x32, 8 warps (4m x 2n), warp tile 64x64, m16n8k16 f16
// mma (fp32 accum), 3-stage cp.async pipeline. SMEM row stride 40 halves
// (80 B) -> banks (20r+lc)%32 all distinct, conflict-free fragment loads.
// EPI: 0=none 1=alpha 2=bias+relu 3=bias+res 4=res. H16OUT: fp16 C store.
#define BM 256
#define BN 128
#define BK 32                            // k-elements per slab (2 x k16)
#define SSTH 40                          // smem row stride (halves) = 80 B
static constexpr int TILE_A_BYTES = BM * SSTH * 2;         // 20480
static constexpr int TILE_B_BYTES = BN * SSTH * 2;         // 10240
static constexpr int STAGE_BYTES  = TILE_A_BYTES + TILE_B_BYTES;  // 30720
static constexpr int NSTAGE       = 3;
static constexpr int SMEM_TOT     = NSTAGE * STAGE_BYTES;  // 92160

template <int EPI, bool H16OUT, bool CSKIP, bool KLIM>
__global__ __launch_bounds__(256)
void mma_gemm(const __half* __restrict__ Ag, const __half* __restrict__ Bg,
              void* __restrict__ Cgv, const float* __restrict__ bias,
              const float* __restrict__ Rg,
              int K, int lda, int ldb, int ldc,
              long long sA, long long sB, long long sC, long long sR,
              float alpha)
{
    const int m0 = blockIdx.y * BM, n0 = blockIdx.x * BN, bz = blockIdx.z;
    if (CSKIP && n0 >= m0 + BM) return;
    Ag += (size_t)bz * sA;
    Bg += (size_t)bz * sB;
    if (EPI == 3 || EPI == 4) Rg += (size_t)bz * sR;

    extern __shared__ char smem[];
    const uint32_t sb = smem_u32(smem);
    const __half* sh = (const __half*)smem;

    const int tid  = threadIdx.x;
    const int wid  = tid >> 5;
    const int lane = tid & 31;
    const int wm   = (wid >> 1) * 64;    // warp m offset (0,64,128,192)
    const int wn   = (wid & 1) * 64;     // warp n offset (0,64)
    const int lr   = lane >> 2;          // 0..7
    const int lc   = lane & 3;           // 0..3

    int kend = K;
    if (KLIM) { int lim = m0 + BM; kend = lim < K ? lim : K; }
    const int T = kend >> 5;

    float acc[4][8][4];
    #pragma unroll
    for (int mi = 0; mi < 4; mi++)
        #pragma unroll
        for (int ni = 0; ni < 8; ni++)
            #pragma unroll
            for (int q = 0; q < 4; q++) acc[mi][ni][q] = 0.f;

    // A: 256 rows x 4 chunks(16B) = 1024; 4 per thread
    auto cpA = [&](int t, int slot) {
        const __half* base = Ag + (size_t)m0 * lda + t * BK;
        const uint32_t db = sb + slot * STAGE_BYTES;
        #pragma unroll
        for (int it = 0; it < 4; it++) {
            const int idx = tid + it * 256;
            const int r = idx >> 2, c4 = idx & 3;
            cpa16(db + (uint32_t)(r * (SSTH * 2) + c4 * 16),
                  base + (size_t)r * lda + c4 * 8);
        }
    };
    // B: 128 rows x 4 chunks = 512; 2 per thread
    auto cpB = [&](int t, int slot) {
        const __half* base = Bg + (size_t)n0 * ldb + t * BK;
        const uint32_t db = sb + slot * STAGE_BYTES + TILE_A_BYTES;
        #pragma unroll
        for (int it = 0; it < 2; it++) {
            const int idx = tid + it * 256;
            const int r = idx >> 2, c4 = idx & 3;
            cpa16(db + (uint32_t)(r * (SSTH * 2) + c4 * 16),
                  base + (size_t)r * ldb + c4 * 8);
        }
    };

    // prologue: stages 0 and 1, separate commit groups
    cpA(0, 0); cpB(0, 0); cp_commit();
    if (T > 1) { cpA(1, 1); cpB(1, 1); cp_commit(); }

    int slot = 0;
    for (int i = 0; i < T; i++) {
        if (i < T - 1) cp_wait1(); else cp_wait0();
        __syncthreads();

        const __half* sa  = sh + (size_t)slot * (STAGE_BYTES / 2);
        const __half* sbb = sa + (TILE_A_BYTES / 2);

        #pragma unroll
        for (int ks = 0; ks < 2; ks++) {
            const int kb = ks * 16;
            uint32_t af[4][4];
            #pragma unroll
            for (int mi = 0; mi < 4; mi++) {
                const int r = wm + mi * 16 + lr;
                const __half* pr0 = sa + (size_t)r * SSTH + kb + 2 * lc;
                const __half* pr1 = pr0 + 8 * SSTH;
                af[mi][0] = *(const uint32_t*)(pr0);
                af[mi][1] = *(const uint32_t*)(pr1);
                af[mi][2] = *(const uint32_t*)(pr0 + 8);
                af[mi][3] = *(const uint32_t*)(pr1 + 8);
            }
            uint32_t bf[8][2];
            #pragma unroll
            for (int ni = 0; ni < 8; ni++) {
                const int n = wn + ni * 8 + lr;
                const __half* pn = sbb + (size_t)n * SSTH + kb + 2 * lc;
                bf[ni][0] = *(const uint32_t*)(pn);
                bf[ni][1] = *(const uint32_t*)(pn + 8);
            }
            #pragma unroll
            for (int mi = 0; mi < 4; mi++)
                #pragma unroll
                for (int ni = 0; ni < 8; ni++)
                    mma_f16_16816(acc[mi][ni][0], acc[mi][ni][1],
                                  acc[mi][ni][2], acc[mi][ni][3],
                                  af[mi][0], af[mi][1], af[mi][2], af[mi][3],
                                  bf[ni][0], bf[ni][1]);
        }

        // prefetch stage i+2 into the slot freed by iteration i-1
        if (i + 2 < T) {
            const int ns = (slot + 2) % NSTAGE;
            cpA(i + 2, ns); cpB(i + 2, ns); cp_commit();
        }
        slot = (slot + 1) % NSTAGE;
    }

    // ---- epilogue: d0,d1 -> (row, col..col+1); d2,d3 -> (row+8, ...) ----
    __half* Ch = (__half*)Cgv + (H16OUT ? (size_t)bz * sC : 0);
    float*  Cf = (float*)Cgv  + (H16OUT ? 0 : (size_t)bz * sC);
    #pragma unroll
    for (int mi = 0; mi < 4; mi++) {
        const int r0 = m0 + wm + mi * 16 + lr;
        #pragma unroll
        for (int ni = 0; ni < 8; ni++) {
            const int col = n0 + wn + ni * 8 + 2 * lc;
            #pragma unroll
            for (int h = 0; h < 2; h++) {
                const int r = r0 + h * 8;
                float vx = acc[mi][ni][2 * h + 0];
                float vy = acc[mi][ni][2 * h + 1];
                const size_t off = (size_t)r * ldc + col;
                if (EPI == 1) {
                    vx *= alpha; vy *= alpha;
                } else if (EPI == 2) {
                    vx = fmaxf(vx + __ldg(bias + col + 0), 0.f);
                    vy = fmaxf(vy + __ldg(bias + col + 1), 0.f);
                } else if (EPI == 3) {
                    float2 rr = *(const float2*)(Rg + off);
                    vx += __ldg(bias + col + 0) + rr.x;
                    vy += __ldg(bias + col + 1) + rr.y;
                } else if (EPI == 4) {
                    float2 rr = *(const float2*)(Rg + off);
                    vx += rr.x; vy += rr.y;
                }
                if (H16OUT) {
                    *(__half2*)(Ch + off) = __floats2half2_rn(vx, vy);
                } else {
                    float2 o2; o2.x = vx; o2.y = vy;
                    *(float2*)(Cf + off) = o2;
                }
            }
        }
    }
}

// ---------------- launcher ------------------------------------------------
extern "C" void kernel_launch(void* const* d_in, const int* in_sizes, int n_in,
                              void* d_out, int out_size)
{
    (void)in_sizes; (void)n_in; (void)out_size;
    const float* x      = (const float*)d_in[0];
    const float* Qw     = (const float*)d_in[1];
    const float* Kw     = (const float*)d_in[2];
    const float* Vw     = (const float*)d_in[3];
    const float* w1     = (const float*)d_in[4];
    const float* b1     = (const float*)d_in[5];
    const float* w2     = (const float*)d_in[6];
    const float* b2     = (const float*)d_in[7];
    const float* gamma1 = (const float*)d_in[8];
    const float* beta1  = (const float*)d_in[9];
    const float* gamma2 = (const float*)d_in[10];
    const float* beta2  = (const float*)d_in[11];
    float* out = (float*)d_out;

    __half *pln1, *pQ, *pK, *pVt, *pS, *pln2, *pH;
    __half *pQwt, *pKwt, *pVwt, *pw1t, *pw2t;
    float *px1;
    cudaGetSymbolAddress((void**)&pln1, g_ln1);
    cudaGetSymbolAddress((void**)&pQ,   g_Q);
    cudaGetSymbolAddress((void**)&pK,   g_K);
    cudaGetSymbolAddress((void**)&pVt,  g_Vt);
    cudaGetSymbolAddress((void**)&pS,   g_S);
    cudaGetSymbolAddress((void**)&px1,  g_x1);
    cudaGetSymbolAddress((void**)&pln2, g_ln2);
    cudaGetSymbolAddress((void**)&pH,   g_H);
    cudaGetSymbolAddress((void**)&pQwt, g_Qwt);
    cudaGetSymbolAddress((void**)&pKwt, g_Kwt);
    cudaGetSymbolAddress((void**)&pVwt, g_Vwt);
    cudaGetSymbolAddress((void**)&pw1t, g_w1t);
    cudaGetSymbolAddress((void**)&pw2t, g_w2t);

    cudaFuncSetAttribute(mma_gemm<0, true,  false, false>,
        cudaFuncAttributeMaxDynamicSharedMemorySize, SMEM_TOT);
    cudaFuncSetAttribute(mma_gemm<1, true,  true,  false>,
        cudaFuncAttributeMaxDynamicSharedMemorySize, SMEM_TOT);
    cudaFuncSetAttribute(mma_gemm<4, false, false, true>,
        cudaFuncAttributeMaxDynamicSharedMemorySize, SMEM_TOT);
    cudaFuncSetAttribute(mma_gemm<2, true,  false, false>,
        cudaFuncAttributeMaxDynamicSharedMemorySize, SMEM_TOT);
    cudaFuncSetAttribute(mma_gemm<3, false, false, false>,
        cudaFuncAttributeMaxDynamicSharedMemorySize, SMEM_TOT);

    const int MR = BB * SS;                 // 8192
    const long long SD  = (long long)SS * DD;
    const long long SSq = (long long)SS * SS;
    const long long DS  = (long long)DD * SS;
    dim3 tb(32, 8);

    // 0) weight transposes (K-major B operands), fp16
    transpose_kernel<<<dim3(DD / 32, DD / 32), tb>>>(Qw, pQwt, DD, DD);
    transpose_kernel<<<dim3(DD / 32, DD / 32), tb>>>(Kw, pKwt, DD, DD);
    transpose_kernel<<<dim3(DD / 32, DD / 32), tb>>>(Vw, pVwt, DD, DD);
    transpose_kernel<<<dim3(FF / 32, DD / 32), tb>>>(w1, pw1t, DD, FF);
    transpose_kernel<<<dim3(DD / 32, FF / 32), tb>>>(w2, pw2t, FF, DD);

    // 1) LN1
    layernorm_kernel<<<MR, 256>>>(x, gamma1, beta1, pln1);

    // 2) Q = ln1 @ Qw ; K = ln1 @ Kw   (M=8192, N=1024, K=1024)
    dim3 gq(DD / BN, MR / BM, 1);
    mma_gemm<0, true, false, false><<<gq, 256, SMEM_TOT>>>(
        pln1, pQwt, pQ, nullptr, nullptr, DD, DD, DD, DD, 0, 0, 0, 0, 1.f);
    mma_gemm<0, true, false, false><<<gq, 256, SMEM_TOT>>>(
        pln1, pKwt, pK, nullptr, nullptr, DD, DD, DD, DD, 0, 0, 0, 0, 1.f);

    // 3) Vt[b,d,s] = sum_k Vwt[d,k] * ln1[b,s,k]   (M=1024, N=2048 per batch)
    dim3 gv(SS / BN, DD / BM, BB);
    mma_gemm<0, true, false, false><<<gv, 256, SMEM_TOT>>>(
        pVwt, pln1, pVt, nullptr, nullptr, DD, DD, DD, SS, 0, SD, DS, 0, 1.f);

    // 4) scores = Q @ K^T / 32, causal tiles only  (M=N=2048, K=1024)
    dim3 gs(SS / BN, SS / BM, BB);
    mma_gemm<1, true, true, false><<<gs, 256, SMEM_TOT>>>(
        pQ, pK, pS, nullptr, nullptr, DD, DD, DD, SS, SD, SD, SSq, 0, 0.03125f);

    // 5) causal softmax (fp16 in/out, zero-padded to 256 boundary)
    softmax_kernel<<<MR, 256>>>(pS);

    // 6) x1 = P @ V + x    (M=2048, N=1024, K<=row band, per batch; fp32 out)
    dim3 gp(DD / BN, SS / BM, BB);
    mma_gemm<4, false, false, true><<<gp, 256, SMEM_TOT>>>(
        pS, pVt, px1, nullptr, x, SS, SS, SS, DD, SSq, DS, SD, SD, 1.f);

    // 7) LN2
    layernorm_kernel<<<MR, 256>>>(px1, gamma2, beta2, pln2);

    // 8) H = relu(ln2 @ w1 + b1)   (M=8192, N=4096, K=1024)
    dim3 g1(FF / BN, MR / BM, 1);
    mma_gemm<2, true, false, false><<<g1, 256, SMEM_TOT>>>(
        pln2, pw1t, pH, b1, nullptr, DD, DD, DD, FF, 0, 0, 0, 0, 1.f);

    // 9) out = H @ w2 + b2 + x1    (M=8192, N=1024, K=4096; fp32 out)
    dim3 g2(DD / BN, MR / BM, 1);
    mma_gemm<3, false, false, false><<<g2, 256, SMEM_TOT>>>(
        pH, pw2t, out, b2, px1, FF, FF, FF, DD, 0, 0, 0, 0, 1.f);
}

// round 14
// speedup vs baseline: 1.8684x; 1.1434x over previous
#include <cuda_runtime.h>
#include <cuda_fp16.h>
#include <cstdint>
#include <math.h>

#define BB 4
#define SS 2048
#define DD 1024
#define FF 4096

// ---------------- scratch (__device__ globals; no allocs allowed) --------
// GEMM operands/outputs in fp16; residual path in fp32.
__device__ __half g_ln1[(size_t)BB * SS * DD];
__device__ __half g_Q  [(size_t)BB * SS * DD];
__device__ __half g_K  [(size_t)BB * SS * DD];
__device__ __half g_Vt [(size_t)BB * DD * SS];   // V transposed: [b][d][s]
__device__ __half g_S  [(size_t)BB * SS * SS];
__device__ float  g_x1 [(size_t)BB * SS * DD];
__device__ __half g_ln2[(size_t)BB * SS * DD];
__device__ __half g_H  [(size_t)BB * SS * FF];
__device__ __half g_Qwt[(size_t)DD * DD];
__device__ __half g_Kwt[(size_t)DD * DD];
__device__ __half g_Vwt[(size_t)DD * DD];
__device__ __half g_w1t[(size_t)DD * FF];
__device__ __half g_w2t[(size_t)DD * FF];

// ---------------- helpers -------------------------------------------------
__device__ __forceinline__ uint32_t smem_u32(const void* p) {
    uint32_t a;
    asm("{ .reg .u64 t; cvta.to.shared.u64 t, %1; cvt.u32.u64 %0, t; }"
        : "=r"(a) : "l"(p));
    return a;
}
__device__ __forceinline__ void cpa16(uint32_t dst, const void* src) {
    asm volatile("cp.async.cg.shared.global [%0], [%1], 16;\n"
                 :: "r"(dst), "l"(src));
}
__device__ __forceinline__ void cp_commit() {
    asm volatile("cp.async.commit_group;\n" ::: "memory");
}
__device__ __forceinline__ void cp_wait1() {
    asm volatile("cp.async.wait_group 1;\n" ::: "memory");
}
__device__ __forceinline__ void cp_wait0() {
    asm volatile("cp.async.wait_group 0;\n" ::: "memory");
}
__device__ __forceinline__ void ldsm4(uint32_t& r0, uint32_t& r1,
                                      uint32_t& r2, uint32_t& r3, uint32_t a) {
    asm volatile("ldmatrix.sync.aligned.m8n8.x4.shared.b16 {%0,%1,%2,%3}, [%4];"
                 : "=r"(r0), "=r"(r1), "=r"(r2), "=r"(r3) : "r"(a));
}
__device__ __forceinline__ void mma_f16_16816(
    float& d0, float& d1, float& d2, float& d3,
    uint32_t a0, uint32_t a1, uint32_t a2, uint32_t a3,
    uint32_t b0, uint32_t b1)
{
    asm volatile(
        "mma.sync.aligned.m16n8k16.row.col.f32.f16.f16.f32 "
        "{%0,%1,%2,%3}, {%4,%5,%6,%7}, {%8,%9}, {%0,%1,%2,%3};"
        : "+f"(d0), "+f"(d1), "+f"(d2), "+f"(d3)
        : "r"(a0), "r"(a1), "r"(a2), "r"(a3), "r"(b0), "r"(b1));
}

// ---------------- LayerNorm (fp32 in -> fp16 out) -------------------------
__global__ __launch_bounds__(256)
void layernorm_kernel(const float* __restrict__ x,
                      const float* __restrict__ gamma,
                      const float* __restrict__ beta,
                      __half* __restrict__ out)
{
    const int row = blockIdx.x;
    const int tid = threadIdx.x;
    float4 v = ((const float4*)(x + (size_t)row * DD))[tid];

    float s  = v.x + v.y + v.z + v.w;
    float sq = v.x * v.x + v.y * v.y + v.z * v.z + v.w * v.w;
    __shared__ float ws[8], wq[8];
    #pragma unroll
    for (int o = 16; o; o >>= 1) {
        s  += __shfl_xor_sync(0xffffffffu, s,  o);
        sq += __shfl_xor_sync(0xffffffffu, sq, o);
    }
    const int w = tid >> 5, l = tid & 31;
    if (l == 0) { ws[w] = s; wq[w] = sq; }
    __syncthreads();
    if (w == 0) {
        s  = (l < 8) ? ws[l] : 0.f;
        sq = (l < 8) ? wq[l] : 0.f;
        #pragma unroll
        for (int o = 4; o; o >>= 1) {
            s  += __shfl_xor_sync(0xffffffffu, s,  o);
            sq += __shfl_xor_sync(0xffffffffu, sq, o);
        }
        if (l == 0) { ws[0] = s; wq[0] = sq; }
    }
    __syncthreads();
    const float mean = ws[0] * (1.f / (float)DD);
    const float var  = wq[0] * (1.f / (float)DD) - mean * mean;
    const float rstd = rsqrtf(var + 1e-5f);
    float4 g = ((const float4*)gamma)[tid];
    float4 b = ((const float4*)beta )[tid];
    __half2 h0 = __floats2half2_rn(g.x * ((v.x - mean) * rstd) + b.x,
                                   g.y * ((v.y - mean) * rstd) + b.y);
    __half2 h1 = __floats2half2_rn(g.z * ((v.z - mean) * rstd) + b.z,
                                   g.w * ((v.w - mean) * rstd) + b.w);
    __half2* o2 = (__half2*)(out + (size_t)row * DD) + tid * 2;
    o2[0] = h0; o2[1] = h1;
}

// ---------------- causal softmax on fp16 scores (256-pad zeroed) ---------
__global__ __launch_bounds__(256)
void softmax_kernel(__half* __restrict__ scores)
{
    const int row = blockIdx.x;
    const int b = row >> 11;
    const int i = row & (SS - 1);
    __half* p = scores + (size_t)b * SS * SS + (size_t)i * SS;
    const int len = i + 1;
    const int tid = threadIdx.x;
    __shared__ float sh[8];

    float m = -1e30f;
    for (int j = tid; j < len; j += 256) m = fmaxf(m, __half2float(p[j]));
    #pragma unroll
    for (int o = 16; o; o >>= 1) m = fmaxf(m, __shfl_xor_sync(0xffffffffu, m, o));
    const int w = tid >> 5, l = tid & 31;
    if (l == 0) sh[w] = m;
    __syncthreads();
    if (w == 0) {
        m = (l < 8) ? sh[l] : -1e30f;
        #pragma unroll
        for (int o = 4; o; o >>= 1) m = fmaxf(m, __shfl_xor_sync(0xffffffffu, m, o));
        if (l == 0) sh[0] = m;
    }
    __syncthreads();
    m = sh[0];
    __syncthreads();

    float sum = 0.f;
    for (int j = tid; j < len; j += 256)
        sum += __expf(__half2float(p[j]) - m);
    #pragma unroll
    for (int o = 16; o; o >>= 1) sum += __shfl_xor_sync(0xffffffffu, sum, o);
    if (l == 0) sh[w] = sum;
    __syncthreads();
    if (w == 0) {
        sum = (l < 8) ? sh[l] : 0.f;
        #pragma unroll
        for (int o = 4; o; o >>= 1) sum += __shfl_xor_sync(0xffffffffu, sum, o);
        if (l == 0) sh[0] = sum;
    }
    __syncthreads();
    const float inv = 1.f / sh[0];
    // zero-pad to the 256 boundary: the K-limited P@V GEMM (BM=256) reads
    // k < m0+256 for every row of its tile.
    const int lenp = (len + 255) & ~255;
    for (int j = tid; j < lenp; j += 256) {
        float e = (j < len) ? __expf(__half2float(p[j]) - m) * inv : 0.f;
        p[j] = __float2half_rn(e);
    }
}

// ---------------- transpose: fp32 in[R,C] -> fp16 out[C,R] ----------------
__global__ __launch_bounds__(256)
void transpose_kernel(const float* __restrict__ in, __half* __restrict__ out,
                      int R, int C)
{
    __shared__ float t[32][33];
    const int c0 = blockIdx.x * 32, r0 = blockIdx.y * 32;
    const int x = threadIdx.x, y = threadIdx.y;
    #pragma unroll
    for (int i = 0; i < 32; i += 8)
        t[y + i][x] = in[(size_t)(r0 + y + i) * C + c0 + x];
    __syncthreads();
    #pragma unroll
    for (int i = 0; i < 32; i += 8)
        out[(size_t)(c0 + y + i) * R + r0 + x] = __float2half_rn(t[x][y + i]);
}

// ---------------- fp16 mma.sync GEMM: C[M,N] = A[M,K] * B[N,K]^T ----------
// CTA tile 256x128x32, 8 warps (4m x 2n), warp tile 64x64, m16n8k16 f16
// mma (fp32 accum), ldmatrix.x4 fragment loads, 3-stage cp.async pipeline.
// SMEM row stride 40 halves (80 B) -> ldmatrix row-address phases hit 8
// distinct banks, conflict-free.
// EPI: 0=none 1=alpha 2=bias+relu 3=bias+res 4=res. H16OUT: fp16 C store.
#define BM 256
#define BN 128
#define BK 32                            // k-elements per slab (2 x k16)
#define SSTH 40                          // smem row stride (halves) = 80 B
static constexpr int TILE_A_BYTES = BM * SSTH * 2;         // 20480
static constexpr int TILE_B_BYTES = BN * SSTH * 2;         // 10240
static constexpr int STAGE_BYTES  = TILE_A_BYTES + TILE_B_BYTES;  // 30720
static constexpr int NSTAGE       = 3;
static constexpr int SMEM_TOT     = NSTAGE * STAGE_BYTES;  // 92160

template <int EPI, bool H16OUT, bool CSKIP, bool KLIM>
__global__ __launch_bounds__(256)
void mma_gemm(const __half* __restrict__ Ag, const __half* __restrict__ Bg,
              void* __restrict__ Cgv, const float* __restrict__ bias,
              const float* __restrict__ Rg,
              int K, int lda, int ldb, int ldc,
              long long sA, long long sB, long long sC, long long sR,
              float alpha)
{
    const int m0 = blockIdx.y * BM, n0 = blockIdx.x * BN, bz = blockIdx.z;
    if (CSKIP && n0 >= m0 + BM) return;
    Ag += (size_t)bz * sA;
    Bg += (size_t)bz * sB;
    if (EPI == 3 || EPI == 4) Rg += (size_t)bz * sR;

    extern __shared__ char smem[];
    const uint32_t sb = smem_u32(smem);

    const int tid  = threadIdx.x;
    const int wid  = tid >> 5;
    const int lane = tid & 31;
    const int wm   = (wid >> 1) * 64;    // warp m offset (0,64,128,192)
    const int wn   = (wid & 1) * 64;     // warp n offset (0,64)
    const int lr   = lane >> 2;          // 0..7
    const int lc   = lane & 3;           // 0..3
    const int l8   = lane & 7;           // row within ldmatrix 8-group
    const int m4   = lane >> 3;          // ldmatrix matrix index 0..3

    int kend = K;
    if (KLIM) { int lim = m0 + BM; kend = lim < K ? lim : K; }
    const int T = kend >> 5;

    float acc[4][8][4];
    #pragma unroll
    for (int mi = 0; mi < 4; mi++)
        #pragma unroll
        for (int ni = 0; ni < 8; ni++)
            #pragma unroll
            for (int q = 0; q < 4; q++) acc[mi][ni][q] = 0.f;

    // A: 256 rows x 4 chunks(16B) = 1024; 4 per thread
    auto cpA = [&](int t, int slot) {
        const __half* base = Ag + (size_t)m0 * lda + t * BK;
        const uint32_t db = sb + slot * STAGE_BYTES;
        #pragma unroll
        for (int it = 0; it < 4; it++) {
            const int idx = tid + it * 256;
            const int r = idx >> 2, c4 = idx & 3;
            cpa16(db + (uint32_t)(r * (SSTH * 2) + c4 * 16),
                  base + (size_t)r * lda + c4 * 8);
        }
    };
    // B: 128 rows x 4 chunks = 512; 2 per thread
    auto cpB = [&](int t, int slot) {
        const __half* base = Bg + (size_t)n0 * ldb + t * BK;
        const uint32_t db = sb + slot * STAGE_BYTES + TILE_A_BYTES;
        #pragma unroll
        for (int it = 0; it < 2; it++) {
            const int idx = tid + it * 256;
            const int r = idx >> 2, c4 = idx & 3;
            cpa16(db + (uint32_t)(r * (SSTH * 2) + c4 * 16),
                  base + (size_t)r * ldb + c4 * 8);
        }
    };

    // prologue: stages 0 and 1, separate commit groups
    cpA(0, 0); cpB(0, 0); cp_commit();
    if (T > 1) { cpA(1, 1); cpB(1, 1); cp_commit(); }

    int slot = 0;
    for (int i = 0; i < T; i++) {
        if (i < T - 1) cp_wait1(); else cp_wait0();
        __syncthreads();

        const uint32_t sa_b  = sb + slot * STAGE_BYTES;
        const uint32_t sbb_b = sa_b + TILE_A_BYTES;

        #pragma unroll
        for (int ks = 0; ks < 2; ks++) {
            const int kb = ks * 16;
            // A fragments: one ldmatrix.x4 per 16-row block.
            // matrix m: rows +(m&1)*8, k half +(m>>1)*8  -> regs a0..a3
            uint32_t af[4][4];
            #pragma unroll
            for (int mi = 0; mi < 4; mi++) {
                const int row = wm + mi * 16 + (m4 & 1) * 8 + l8;
                const uint32_t a = sa_b + (uint32_t)(row * (SSTH * 2)
                                   + (kb + (m4 >> 1) * 8) * 2);
                ldsm4(af[mi][0], af[mi][1], af[mi][2], af[mi][3], a);
            }
            // B fragments: one ldmatrix.x4 per 16-n block (2 ni values).
            // matrix m: n +(m>>1)*8, k half +(m&1)*8
            uint32_t bf[8][2];
            #pragma unroll
            for (int nj = 0; nj < 4; nj++) {
                const int n = wn + nj * 16 + (m4 >> 1) * 8 + l8;
                const uint32_t a = sbb_b + (uint32_t)(n * (SSTH * 2)
                                   + (kb + (m4 & 1) * 8) * 2);
                ldsm4(bf[2 * nj][0], bf[2 * nj][1],
                      bf[2 * nj + 1][0], bf[2 * nj + 1][1], a);
            }
            #pragma unroll
            for (int mi = 0; mi < 4; mi++)
                #pragma unroll
                for (int ni = 0; ni < 8; ni++)
                    mma_f16_16816(acc[mi][ni][0], acc[mi][ni][1],
                                  acc[mi][ni][2], acc[mi][ni][3],
                                  af[mi][0], af[mi][1], af[mi][2], af[mi][3],
                                  bf[ni][0], bf[ni][1]);
        }

        // prefetch stage i+2 into the slot freed by iteration i-1
        if (i + 2 < T) {
            const int ns = (slot + 2) % NSTAGE;
            cpA(i + 2, ns); cpB(i + 2, ns); cp_commit();
        }
        slot = (slot + 1) % NSTAGE;
    }

    // ---- epilogue: d0,d1 -> (row, col..col+1); d2,d3 -> (row+8, ...) ----
    __half* Ch = (__half*)Cgv + (H16OUT ? (size_t)bz * sC : 0);
    float*  Cf = (float*)Cgv  + (H16OUT ? 0 : (size_t)bz * sC);
    #pragma unroll
    for (int mi = 0; mi < 4; mi++) {
        const int r0 = m0 + wm + mi * 16 + lr;
        #pragma unroll
        for (int ni = 0; ni < 8; ni++) {
            const int col = n0 + wn + ni * 8 + 2 * lc;
            #pragma unroll
            for (int h = 0; h < 2; h++) {
                const int r = r0 + h * 8;
                float vx = acc[mi][ni][2 * h + 0];
                float vy = acc[mi][ni][2 * h + 1];
                const size_t off = (size_t)r * ldc + col;
                if (EPI == 1) {
                    vx *= alpha; vy *= alpha;
                } else if (EPI == 2) {
                    vx = fmaxf(vx + __ldg(bias + col + 0), 0.f);
                    vy = fmaxf(vy + __ldg(bias + col + 1), 0.f);
                } else if (EPI == 3) {
                    float2 rr = *(const float2*)(Rg + off);
                    vx += __ldg(bias + col + 0) + rr.x;
                    vy += __ldg(bias + col + 1) + rr.y;
                } else if (EPI == 4) {
                    float2 rr = *(const float2*)(Rg + off);
                    vx += rr.x; vy += rr.y;
                }
                if (H16OUT) {
                    *(__half2*)(Ch + off) = __floats2half2_rn(vx, vy);
                } else {
                    float2 o2; o2.x = vx; o2.y = vy;
                    *(float2*)(Cf + off) = o2;
                }
            }
        }
    }
}

// ---------------- launcher ------------------------------------------------
extern "C" void kernel_launch(void* const* d_in, const int* in_sizes, int n_in,
                              void* d_out, int out_size)
{
    (void)in_sizes; (void)n_in; (void)out_size;
    const float* x      = (const float*)d_in[0];
    const float* Qw     = (const float*)d_in[1];
    const float* Kw     = (const float*)d_in[2];
    const float* Vw     = (const float*)d_in[3];
    const float* w1     = (const float*)d_in[4];
    const float* b1     = (const float*)d_in[5];
    const float* w2     = (const float*)d_in[6];
    const float* b2     = (const float*)d_in[7];
    const float* gamma1 = (const float*)d_in[8];
    const float* beta1  = (const float*)d_in[9];
    const float* gamma2 = (const float*)d_in[10];
    const float* beta2  = (const float*)d_in[11];
    float* out = (float*)d_out;

    __half *pln1, *pQ, *pK, *pVt, *pS, *pln2, *pH;
    __half *pQwt, *pKwt, *pVwt, *pw1t, *pw2t;
    float *px1;
    cudaGetSymbolAddress((void**)&pln1, g_ln1);
    cudaGetSymbolAddress((void**)&pQ,   g_Q);
    cudaGetSymbolAddress((void**)&pK,   g_K);
    cudaGetSymbolAddress((void**)&pVt,  g_Vt);
    cudaGetSymbolAddress((void**)&pS,   g_S);
    cudaGetSymbolAddress((void**)&px1,  g_x1);
    cudaGetSymbolAddress((void**)&pln2, g_ln2);
    cudaGetSymbolAddress((void**)&pH,   g_H);
    cudaGetSymbolAddress((void**)&pQwt, g_Qwt);
    cudaGetSymbolAddress((void**)&pKwt, g_Kwt);
    cudaGetSymbolAddress((void**)&pVwt, g_Vwt);
    cudaGetSymbolAddress((void**)&pw1t, g_w1t);
    cudaGetSymbolAddress((void**)&pw2t, g_w2t);

    cudaFuncSetAttribute(mma_gemm<0, true,  false, false>,
        cudaFuncAttributeMaxDynamicSharedMemorySize, SMEM_TOT);
    cudaFuncSetAttribute(mma_gemm<1, true,  true,  false>,
        cudaFuncAttributeMaxDynamicSharedMemorySize, SMEM_TOT);
    cudaFuncSetAttribute(mma_gemm<4, false, false, true>,
        cudaFuncAttributeMaxDynamicSharedMemorySize, SMEM_TOT);
    cudaFuncSetAttribute(mma_gemm<2, true,  false, false>,
        cudaFuncAttributeMaxDynamicSharedMemorySize, SMEM_TOT);
    cudaFuncSetAttribute(mma_gemm<3, false, false, false>,
        cudaFuncAttributeMaxDynamicSharedMemorySize, SMEM_TOT);

    const int MR = BB * SS;                 // 8192
    const long long SD  = (long long)SS * DD;
    const long long SSq = (long long)SS * SS;
    const long long DS  = (long long)DD * SS;
    dim3 tb(32, 8);

    // 0) weight transposes (K-major B operands), fp16
    transpose_kernel<<<dim3(DD / 32, DD / 32), tb>>>(Qw, pQwt, DD, DD);
    transpose_kernel<<<dim3(DD / 32, DD / 32), tb>>>(Kw, pKwt, DD, DD);
    transpose_kernel<<<dim3(DD / 32, DD / 32), tb>>>(Vw, pVwt, DD, DD);
    transpose_kernel<<<dim3(FF / 32, DD / 32), tb>>>(w1, pw1t, DD, FF);
    transpose_kernel<<<dim3(DD / 32, FF / 32), tb>>>(w2, pw2t, FF, DD);

    // 1) LN1
    layernorm_kernel<<<MR, 256>>>(x, gamma1, beta1, pln1);

    // 2) Q = ln1 @ Qw ; K = ln1 @ Kw   (M=8192, N=1024, K=1024)
    dim3 gq(DD / BN, MR / BM, 1);
    mma_gemm<0, true, false, false><<<gq, 256, SMEM_TOT>>>(
        pln1, pQwt, pQ, nullptr, nullptr, DD, DD, DD, DD, 0, 0, 0, 0, 1.f);
    mma_gemm<0, true, false, false><<<gq, 256, SMEM_TOT>>>(
        pln1, pKwt, pK, nullptr, nullptr, DD, DD, DD, DD, 0, 0, 0, 0, 1.f);

    // 3) Vt[b,d,s] = sum_k Vwt[d,k] * ln1[b,s,k]   (M=1024, N=2048 per batch)
    dim3 gv(SS / BN, DD / BM, BB);
    mma_gemm<0, true, false, false><<<gv, 256, SMEM_TOT>>>(
        pVwt, pln1, pVt, nullptr, nullptr, DD, DD, DD, SS, 0, SD, DS, 0, 1.f);

    // 4) scores = Q @ K^T / 32, causal tiles only  (M=N=2048, K=1024)
    dim3 gs(SS / BN, SS / BM, BB);
    mma_gemm<1, true, true, false><<<gs, 256, SMEM_TOT>>>(
        pQ, pK, pS, nullptr, nullptr, DD, DD, DD, SS, SD, SD, SSq, 0, 0.03125f);

    // 5) causal softmax (fp16 in/out, zero-padded to 256 boundary)
    softmax_kernel<<<MR, 256>>>(pS);

    // 6) x1 = P @ V + x    (M=2048, N=1024, K<=row band, per batch; fp32 out)
    dim3 gp(DD / BN, SS / BM, BB);
    mma_gemm<4, false, false, true><<<gp, 256, SMEM_TOT>>>(
        pS, pVt, px1, nullptr, x, SS, SS, SS, DD, SSq, DS, SD, SD, 1.f);

    // 7) LN2
    layernorm_kernel<<<MR, 256>>>(px1, gamma2, beta2, pln2);

    // 8) H = relu(ln2 @ w1 + b1)   (M=8192, N=4096, K=1024)
    dim3 g1(FF / BN, MR / BM, 1);
    mma_gemm<2, true, false, false><<<g1, 256, SMEM_TOT>>>(
        pln2, pw1t, pH, b1, nullptr, DD, DD, DD, FF, 0, 0, 0, 0, 1.f);

    // 9) out = H @ w2 + b2 + x1    (M=8192, N=1024, K=4096; fp32 out)
    dim3 g2(DD / BN, MR / BM, 1);
    mma_gemm<3, false, false, false><<<g2, 256, SMEM_TOT>>>(
        pH, pw2t, out, b2, px1, FF, FF, FF, DD, 0, 0, 0, 0, 1.f);
}